// round 2
// baseline (speedup 1.0000x reference)
#include <cuda_runtime.h>
#include <cuda_bf16.h>
#include <math.h>

// Problem constants
#define BB 64
#define SS 512
#define EE 256
#define HH 512
#define G3 1536
#define TT 64
#define NCTA 128

// ---------------- device scratch ----------------
__device__ float g_gi[(size_t)SS * G3 * BB];       // [s][col][b]   201 MB
__device__ float g_states[(size_t)SS * BB * HH];   // [s][b][j]     64 MB
__device__ float g_h[2 * HH * BB];                 // [buf][k][b]   256 KB
__device__ unsigned int g_bar;
__device__ int g_tok64;

// ---------------- f32x2 helpers ----------------
__device__ __forceinline__ unsigned long long ffma2(unsigned long long a,
                                                    unsigned long long b,
                                                    unsigned long long c) {
    unsigned long long d;
    asm("fma.rn.f32x2 %0, %1, %2, %3;" : "=l"(d) : "l"(a), "l"(b), "l"(c));
    return d;
}
__device__ __forceinline__ unsigned long long pack2(float lo, float hi) {
    unsigned long long r;
    asm("mov.b64 %0, {%1, %2};" : "=l"(r) : "f"(lo), "f"(hi));
    return r;
}
__device__ __forceinline__ float2 unpack2(unsigned long long v) {
    float2 f;
    asm("mov.b64 {%0, %1}, %2;" : "=f"(f.x), "=f"(f.y) : "l"(v));
    return f;
}
__device__ __forceinline__ unsigned long long shfl_xor64(unsigned long long v, int m) {
    unsigned lo = (unsigned)v, hi = (unsigned)(v >> 32);
    lo = __shfl_xor_sync(0xffffffffu, lo, m);
    hi = __shfl_xor_sync(0xffffffffu, hi, m);
    return ((unsigned long long)hi << 32) | lo;
}
__device__ __forceinline__ unsigned long long add2(unsigned long long a, unsigned long long b) {
    unsigned long long d;
    asm("add.rn.f32x2 %0, %1, %2;" : "=l"(d) : "l"(a), "l"(b));
    return d;
}
__device__ __forceinline__ int get_tok(const void* t, int i) {
    if (g_tok64) return (int)((const long long*)t)[i];
    return ((const int*)t)[i];
}

// ---------------- init: zero h, reset barrier, detect token width ----------------
__global__ void init_kernel(const void* __restrict__ tokens) {
    int tid = blockIdx.x * blockDim.x + threadIdx.x;
    // zero both h buffers (2*512*64 = 65536 floats) with 64*256=16384 threads
    for (int i = tid; i < 2 * HH * BB; i += 64 * 256) g_h[i] = 0.0f;
    if (blockIdx.x == 0 && threadIdx.x == 0) {
        g_bar = 0u;
        const long long* tt = (const long long*)tokens;
        int ok = 1;
        for (int i = 0; i < 128; i++) {
            long long v = tt[i];
            if (v < 0 || v >= 50000) { ok = 0; break; }
        }
        g_tok64 = ok;
    }
}

// ---------------- Phase 1: GI = emb[tok] @ W_ih^T + b_ih ----------------
// grid (12, 512): bx = 128-col tile, by = s. BM=64(b), BN=128, BK=32, thread 4x8.
__global__ __launch_bounds__(256) void gi_kernel(const void* __restrict__ tokens,
                                                 const float* __restrict__ emb,
                                                 const float* __restrict__ W_ih,
                                                 const float* __restrict__ b_ih) {
    __shared__ __align__(16) float As[64 * 36];
    __shared__ __align__(16) float Bs[128 * 36];
    __shared__ int toks[64];

    const int tid = threadIdx.x;
    const int s = blockIdx.y;
    const int colbase = blockIdx.x * 128;
    const int tx = tid & 15, ty = tid >> 4;
    const int ty4 = ty * 4, tx8 = tx * 8;

    if (tid < 64) toks[tid] = get_tok(tokens, tid * SS + s);
    __syncthreads();

    unsigned long long acc[4][8];
#pragma unroll
    for (int i = 0; i < 4; i++)
#pragma unroll
        for (int j = 0; j < 8; j++) acc[i][j] = 0ull;

    for (int k0 = 0; k0 < EE; k0 += 32) {
        // load A: 64 rows x 32 k; 2 float4 per thread
#pragma unroll
        for (int j = 0; j < 2; j++) {
            int f = tid * 2 + j;
            int r = f >> 3, kq = f & 7;
            float4 v = *(const float4*)(emb + (size_t)toks[r] * EE + k0 + kq * 4);
            *(float4*)&As[r * 36 + kq * 4] = v;
        }
        // load B: 128 cols x 32 k; 4 float4 per thread
#pragma unroll
        for (int j = 0; j < 4; j++) {
            int f = tid * 4 + j;
            int c = f >> 3, kq = f & 7;
            float4 v = *(const float4*)(W_ih + (size_t)(colbase + c) * EE + k0 + kq * 4);
            *(float4*)&Bs[c * 36 + kq * 4] = v;
        }
        __syncthreads();

#pragma unroll
        for (int k = 0; k < 32; k += 4) {
            ulonglong2 a2[4];
#pragma unroll
            for (int i = 0; i < 4; i++)
                a2[i] = *(const ulonglong2*)&As[(ty4 + i) * 36 + k];
#pragma unroll
            for (int j = 0; j < 8; j++) {
                ulonglong2 b2 = *(const ulonglong2*)&Bs[(tx8 + j) * 36 + k];
#pragma unroll
                for (int i = 0; i < 4; i++) {
                    acc[i][j] = ffma2(a2[i].x, b2.x, acc[i][j]);
                    acc[i][j] = ffma2(a2[i].y, b2.y, acc[i][j]);
                }
            }
        }
        __syncthreads();
    }

    // store to g_gi[s][col][b], fold b_ih
#pragma unroll
    for (int j = 0; j < 8; j++) {
        int col = colbase + tx8 + j;
        float bias = b_ih[col];
        size_t base = ((size_t)s * G3 + col) * BB;
#pragma unroll
        for (int i = 0; i < 4; i++) {
            float2 v = unpack2(acc[i][j]);
            g_gi[base + ty4 + i] = v.x + v.y + bias;
        }
    }
}

// ---------------- Phase 2: persistent GRU recurrence ----------------
// 128 CTAs; CTA owns 4 hidden units (12 W_hh rows resident in smem as [k][c]).
// lane = bl*4+kg: bl in 0..7 (batch within warp), kg in 0..3 (k-split).
__global__ __launch_bounds__(256, 1) void gru_kernel(const float* __restrict__ W_hh,
                                                     const float* __restrict__ b_hh) {
    __shared__ __align__(16) float w_s[HH * 12];  // [k][c], c = gate*4+u  (24 KB)
    __shared__ float bhh_s[12];

    const int tid = threadIdx.x;
    const int j0 = blockIdx.x * 4;
    const int warp = tid >> 5, lane = tid & 31;
    const int bl = lane >> 2, kg = lane & 3;
    const int b = warp * 8 + bl;

    // load W_hh slice: w_s[k][c] = W_hh[gate*512 + j0 + u][k]
    for (int idx = tid; idx < HH * 12; idx += 256) {
        int k = idx / 12, c = idx % 12;
        int gate = c >> 2, u = c & 3;
        w_s[k * 12 + c] = W_hh[(size_t)(gate * HH + j0 + u) * HH + k];
    }
    if (tid < 12) {
        int gate = tid >> 2, u = tid & 3;
        bhh_s[tid] = b_hh[gate * HH + j0 + u];
    }
    __syncthreads();

    for (int s = 0; s < SS; s++) {
        const int cur = s & 1, nxt = cur ^ 1;
        const float* __restrict__ hc = g_h + cur * (HH * BB);

        unsigned long long acc[6] = {0ull, 0ull, 0ull, 0ull, 0ull, 0ull};
#pragma unroll 4
        for (int i = 0; i < 128; i++) {
            int k = (i << 2) + kg;
            float hv = __ldcg(hc + k * BB + b);
            unsigned long long h2 = pack2(hv, hv);
            const ulonglong2* wp = (const ulonglong2*)(w_s + k * 12);
            ulonglong2 w0 = wp[0], w1 = wp[1], w2v = wp[2];
            acc[0] = ffma2(h2, w0.x, acc[0]);
            acc[1] = ffma2(h2, w0.y, acc[1]);
            acc[2] = ffma2(h2, w1.x, acc[2]);
            acc[3] = ffma2(h2, w1.y, acc[3]);
            acc[4] = ffma2(h2, w2v.x, acc[4]);
            acc[5] = ffma2(h2, w2v.y, acc[5]);
        }
        // reduce across the 4 k-split lanes
#pragma unroll
        for (int j = 0; j < 6; j++) {
            acc[j] = add2(acc[j], shfl_xor64(acc[j], 1));
            acc[j] = add2(acc[j], shfl_xor64(acc[j], 2));
        }

        if (kg == 0) {
            float gh[12];
#pragma unroll
            for (int j = 0; j < 6; j++) {
                float2 v = unpack2(acc[j]);
                gh[2 * j] = v.x;
                gh[2 * j + 1] = v.y;
            }
            const float* gis = g_gi + (size_t)s * G3 * BB;
            float hnew[4];
#pragma unroll
            for (int u = 0; u < 4; u++) {
                float gir = gis[(size_t)(j0 + u) * BB + b];
                float giz = gis[(size_t)(HH + j0 + u) * BB + b];
                float gin = gis[(size_t)(2 * HH + j0 + u) * BB + b];
                float ghr = gh[u] + bhh_s[u];
                float ghz = gh[4 + u] + bhh_s[4 + u];
                float ghn = gh[8 + u] + bhh_s[8 + u];
                float r = 1.0f / (1.0f + expf(-(gir + ghr)));
                float z = 1.0f / (1.0f + expf(-(giz + ghz)));
                float n = tanhf(gin + r * ghn);
                float hp = __ldcg(hc + (j0 + u) * BB + b);
                hnew[u] = (1.0f - z) * n + z * hp;
            }
            float* hnx = g_h + nxt * (HH * BB);
#pragma unroll
            for (int u = 0; u < 4; u++) hnx[(j0 + u) * BB + b] = hnew[u];
            *(float4*)(g_states + ((size_t)s * BB + b) * HH + j0) =
                make_float4(hnew[0], hnew[1], hnew[2], hnew[3]);
        }

        // grid barrier (monotonic generation counter)
        __threadfence();
        __syncthreads();
        if (tid == 0) {
            unsigned target = (unsigned)NCTA * (unsigned)(s + 1);
            atomicAdd(&g_bar, 1u);
            unsigned v;
            do {
                asm volatile("ld.global.acquire.gpu.u32 %0, [%1];"
                             : "=r"(v) : "l"(&g_bar));
            } while (v < target);
        }
        __syncthreads();
    }
}

// ---------------- Phase 3: tag logits = states @ W_tag^T + b_tag ----------------
// grid 512 (one s per CTA). 64 b x 64 t outputs; BK=32; thread 4x4.
__global__ __launch_bounds__(256) void tag_kernel(const float* __restrict__ W_tag,
                                                  const float* __restrict__ b_tag,
                                                  float* __restrict__ out) {
    __shared__ __align__(16) float As[64 * 36];
    __shared__ __align__(16) float Ws[64 * 36];

    const int tid = threadIdx.x;
    const int s = blockIdx.x;
    const int tx = tid & 15, ty = tid >> 4;
    const int b4 = ty * 4, t4 = tx * 4;

    unsigned long long acc[4][4];
#pragma unroll
    for (int i = 0; i < 4; i++)
#pragma unroll
        for (int j = 0; j < 4; j++) acc[i][j] = 0ull;

    for (int k0 = 0; k0 < HH; k0 += 32) {
#pragma unroll
        for (int j = 0; j < 2; j++) {
            int f = tid * 2 + j;
            int r = f >> 3, kq = f & 7;
            float4 v = *(const float4*)(g_states + ((size_t)s * BB + r) * HH + k0 + kq * 4);
            *(float4*)&As[r * 36 + kq * 4] = v;
            float4 w = *(const float4*)(W_tag + (size_t)r * HH + k0 + kq * 4);
            *(float4*)&Ws[r * 36 + kq * 4] = w;
        }
        __syncthreads();
#pragma unroll
        for (int k = 0; k < 32; k += 4) {
            ulonglong2 a2[4];
#pragma unroll
            for (int i = 0; i < 4; i++)
                a2[i] = *(const ulonglong2*)&As[(b4 + i) * 36 + k];
#pragma unroll
            for (int j = 0; j < 4; j++) {
                ulonglong2 w2 = *(const ulonglong2*)&Ws[(t4 + j) * 36 + k];
#pragma unroll
                for (int i = 0; i < 4; i++) {
                    acc[i][j] = ffma2(a2[i].x, w2.x, acc[i][j]);
                    acc[i][j] = ffma2(a2[i].y, w2.y, acc[i][j]);
                }
            }
        }
        __syncthreads();
    }

#pragma unroll
    for (int j = 0; j < 4; j++) {
        int t = t4 + j;
        float bias = b_tag[t];
#pragma unroll
        for (int i = 0; i < 4; i++) {
            int bb = b4 + i;
            float2 v = unpack2(acc[i][j]);
            out[((size_t)bb * SS + s) * TT + t] = v.x + v.y + bias;
        }
    }
}

// ---------------- Phase 4: masked argmax preds ----------------
__global__ void pred_kernel(const void* __restrict__ tokens,
                            float* __restrict__ out, int out_size) {
    const int i = blockIdx.x * blockDim.x + threadIdx.x;  // i = b*512 + s
    if (i >= BB * SS) return;
    const float* lg = out + (size_t)i * TT;
    float best = lg[0];
    int bi = 0;
#pragma unroll 8
    for (int t = 1; t < TT; t++) {
        float v = lg[t];
        if (v > best) { best = v; bi = t; }
    }
    int tk = get_tok(tokens, i);
    long long pred = (tk != 0) ? (long long)bi : 0ll;

    const int NLOGIT = BB * SS * TT;  // 2097152
    int rem = out_size - NLOGIT;
    if (rem >= 2 * BB * SS) {
        long long* po = (long long*)((char*)out + (size_t)NLOGIT * 4);
        po[i] = pred;
    } else if (rem >= BB * SS) {
        out[NLOGIT + i] = (float)pred;
    }
}

// ---------------- launch ----------------
extern "C" void kernel_launch(void* const* d_in, const int* in_sizes, int n_in,
                              void* d_out, int out_size) {
    const void* tokens = d_in[0];
    const float* emb = (const float*)d_in[1];
    const float* W_ih = (const float*)d_in[2];
    const float* W_hh = (const float*)d_in[3];
    const float* b_ih = (const float*)d_in[4];
    const float* b_hh = (const float*)d_in[5];
    const float* W_tag = (const float*)d_in[6];
    const float* b_tag = (const float*)d_in[7];
    float* out = (float*)d_out;

    init_kernel<<<64, 256>>>(tokens);
    gi_kernel<<<dim3(12, 512), 256>>>(tokens, emb, W_ih, b_ih);
    gru_kernel<<<NCTA, 256>>>(W_hh, b_hh);
    tag_kernel<<<SS, 256>>>(W_tag, b_tag, out);
    pred_kernel<<<128, 256>>>(tokens, out, out_size);
}

// round 3
// speedup vs baseline: 1.1544x; 1.1544x over previous
#include <cuda_runtime.h>
#include <cuda_bf16.h>
#include <math.h>

// Problem constants
#define BB 64
#define SS 512
#define EE 256
#define HH 512
#define G3 1536
#define TT 64
#define NCTA 128

// ---------------- device scratch ----------------
__device__ float g_gi[(size_t)SS * G3 * BB];       // [s][col][b]   201 MB
__device__ float g_states[(size_t)SS * BB * HH];   // [s][b][j]     64 MB
__device__ float4 g_h4[2][HH / 4][BB];             // [buf][k>>2][b] 256 KB
__device__ unsigned int g_bar;
__device__ int g_tok64;

// ---------------- f32x2 helpers ----------------
__device__ __forceinline__ unsigned long long ffma2(unsigned long long a,
                                                    unsigned long long b,
                                                    unsigned long long c) {
    unsigned long long d;
    asm("fma.rn.f32x2 %0, %1, %2, %3;" : "=l"(d) : "l"(a), "l"(b), "l"(c));
    return d;
}
__device__ __forceinline__ unsigned long long pack2(float lo, float hi) {
    unsigned long long r;
    asm("mov.b64 %0, {%1, %2};" : "=l"(r) : "f"(lo), "f"(hi));
    return r;
}
__device__ __forceinline__ float2 unpack2(unsigned long long v) {
    float2 f;
    asm("mov.b64 {%0, %1}, %2;" : "=f"(f.x), "=f"(f.y) : "l"(v));
    return f;
}
__device__ __forceinline__ unsigned long long shfl_xor64(unsigned long long v, int m) {
    unsigned lo = (unsigned)v, hi = (unsigned)(v >> 32);
    lo = __shfl_xor_sync(0xffffffffu, lo, m);
    hi = __shfl_xor_sync(0xffffffffu, hi, m);
    return ((unsigned long long)hi << 32) | lo;
}
__device__ __forceinline__ unsigned long long add2(unsigned long long a, unsigned long long b) {
    unsigned long long d;
    asm("add.rn.f32x2 %0, %1, %2;" : "=l"(d) : "l"(a), "l"(b));
    return d;
}
__device__ __forceinline__ int get_tok(const void* t, int i) {
    if (g_tok64) return (int)((const long long*)t)[i];
    return ((const int*)t)[i];
}
__device__ __forceinline__ float fast_sigmoid(float x) {
    return 1.0f / (1.0f + __expf(-x));
}
__device__ __forceinline__ float fast_tanh(float x) {
    // tanh(x) = 1 - 2/(exp(2x)+1), __expf rel err ~1e-7
    return 1.0f - 2.0f / (__expf(2.0f * x) + 1.0f);
}

// ---------------- init: zero h, reset barrier, detect token width ----------------
__global__ void init_kernel(const void* __restrict__ tokens) {
    int tid = blockIdx.x * blockDim.x + threadIdx.x;
    float* hz = (float*)g_h4;
    for (int i = tid; i < 2 * HH * BB; i += 64 * 256) hz[i] = 0.0f;
    if (blockIdx.x == 0 && threadIdx.x == 0) {
        g_bar = 0u;
        const long long* tt = (const long long*)tokens;
        int ok = 1;
        for (int i = 0; i < 128; i++) {
            long long v = tt[i];
            if (v < 0 || v >= 50000) { ok = 0; break; }
        }
        g_tok64 = ok;
    }
}

// ---------------- Phase 1: GI = emb[tok] @ W_ih^T + b_ih ----------------
__global__ __launch_bounds__(256) void gi_kernel(const void* __restrict__ tokens,
                                                 const float* __restrict__ emb,
                                                 const float* __restrict__ W_ih,
                                                 const float* __restrict__ b_ih) {
    __shared__ __align__(16) float As[64 * 36];
    __shared__ __align__(16) float Bs[128 * 36];
    __shared__ int toks[64];

    const int tid = threadIdx.x;
    const int s = blockIdx.y;
    const int colbase = blockIdx.x * 128;
    const int tx = tid & 15, ty = tid >> 4;
    const int ty4 = ty * 4, tx8 = tx * 8;

    if (tid < 64) toks[tid] = get_tok(tokens, tid * SS + s);
    __syncthreads();

    unsigned long long acc[4][8];
#pragma unroll
    for (int i = 0; i < 4; i++)
#pragma unroll
        for (int j = 0; j < 8; j++) acc[i][j] = 0ull;

    for (int k0 = 0; k0 < EE; k0 += 32) {
#pragma unroll
        for (int j = 0; j < 2; j++) {
            int f = tid * 2 + j;
            int r = f >> 3, kq = f & 7;
            float4 v = *(const float4*)(emb + (size_t)toks[r] * EE + k0 + kq * 4);
            *(float4*)&As[r * 36 + kq * 4] = v;
        }
#pragma unroll
        for (int j = 0; j < 4; j++) {
            int f = tid * 4 + j;
            int c = f >> 3, kq = f & 7;
            float4 v = *(const float4*)(W_ih + (size_t)(colbase + c) * EE + k0 + kq * 4);
            *(float4*)&Bs[c * 36 + kq * 4] = v;
        }
        __syncthreads();

#pragma unroll
        for (int k = 0; k < 32; k += 4) {
            ulonglong2 a2[4];
#pragma unroll
            for (int i = 0; i < 4; i++)
                a2[i] = *(const ulonglong2*)&As[(ty4 + i) * 36 + k];
#pragma unroll
            for (int j = 0; j < 8; j++) {
                ulonglong2 b2 = *(const ulonglong2*)&Bs[(tx8 + j) * 36 + k];
#pragma unroll
                for (int i = 0; i < 4; i++) {
                    acc[i][j] = ffma2(a2[i].x, b2.x, acc[i][j]);
                    acc[i][j] = ffma2(a2[i].y, b2.y, acc[i][j]);
                }
            }
        }
        __syncthreads();
    }

#pragma unroll
    for (int j = 0; j < 8; j++) {
        int col = colbase + tx8 + j;
        float bias = b_ih[col];
        size_t base = ((size_t)s * G3 + col) * BB;
#pragma unroll
        for (int i = 0; i < 4; i++) {
            float2 v = unpack2(acc[i][j]);
            g_gi[base + ty4 + i] = v.x + v.y + bias;
        }
    }
}

// ---------------- Phase 2: persistent GRU recurrence ----------------
// 128 CTAs, 256 threads. CTA owns 4 hidden units (12 gh columns).
// lane = bl*4+kg: bl 0..7 (batch-in-warp), kg 0..3 (k-split, 128 k each).
// h stored as float4 [k>>2][b]; weights in smem, skewed to kill bank conflicts.
#define WSKEW(k) ((k) * 12 + (((k) >> 7) << 2))
__global__ __launch_bounds__(256, 1) void gru_kernel(const float* __restrict__ W_hh,
                                                     const float* __restrict__ b_hh) {
    __shared__ __align__(16) float w_s[HH * 12 + 16];  // skewed [k][c]
    __shared__ float bhh_s[12];

    const int tid = threadIdx.x;
    const int j0 = blockIdx.x * 4;
    const int warp = tid >> 5, lane = tid & 31;
    const int bl = lane >> 2, kg = lane & 3;
    const int b = warp * 8 + bl;

    for (int idx = tid; idx < HH * 12; idx += 256) {
        int k = idx / 12, c = idx % 12;
        int gate = c >> 2, u = c & 3;
        w_s[WSKEW(k) + c] = W_hh[(size_t)(gate * HH + j0 + u) * HH + k];
    }
    if (tid < 12) {
        int gate = tid >> 2, u = tid & 3;
        bhh_s[tid] = b_hh[gate * HH + j0 + u];
    }
    __syncthreads();

    const int kq0 = kg * 32;                  // this lane's float4-k range
    const float* wbase = w_s + WSKEW(kg * 128);  // skew folded into base
    float hprev0 = 0.0f, hprev1 = 0.0f, hprev2 = 0.0f, hprev3 = 0.0f;

    for (int s = 0; s < SS; s++) {
        const int cur = s & 1, nxt = cur ^ 1;
        const float4* __restrict__ hc = &g_h4[cur][0][0];

        // prefetch gi for this step (consumed after mainloop, ~3K cyc later)
        float gir[4], giz[4], gin[4];
        if (kg == 0) {
            const float* gis = g_gi + (size_t)s * G3 * BB;
#pragma unroll
            for (int u = 0; u < 4; u++) {
                gir[u] = __ldcs(gis + (size_t)(j0 + u) * BB + b);
                giz[u] = __ldcs(gis + (size_t)(HH + j0 + u) * BB + b);
                gin[u] = __ldcs(gis + (size_t)(2 * HH + j0 + u) * BB + b);
            }
        }

        unsigned long long acc[6] = {0ull, 0ull, 0ull, 0ull, 0ull, 0ull};

        // software-pipelined mainloop: 32 float4 h loads in groups of 8
        float4 hA[8], hB[8];
#pragma unroll
        for (int i = 0; i < 8; i++) hA[i] = __ldcg(&hc[(kq0 + i) * BB + b]);

#pragma unroll
        for (int g = 0; g < 4; g++) {
            if (g < 3) {
#pragma unroll
                for (int i = 0; i < 8; i++)
                    hB[i] = __ldcg(&hc[(kq0 + (g + 1) * 8 + i) * BB + b]);
            }
#pragma unroll
            for (int i = 0; i < 8; i++) {
                const float hv[4] = {hA[i].x, hA[i].y, hA[i].z, hA[i].w};
#pragma unroll
                for (int j = 0; j < 4; j++) {
                    int kk = (g * 8 + i) * 4 + j;          // k within this kg's 128
                    const ulonglong2* wp = (const ulonglong2*)(wbase + kk * 12);
                    unsigned long long h2 = pack2(hv[j], hv[j]);
                    ulonglong2 w0 = wp[0], w1 = wp[1], w2v = wp[2];
                    acc[0] = ffma2(h2, w0.x, acc[0]);
                    acc[1] = ffma2(h2, w0.y, acc[1]);
                    acc[2] = ffma2(h2, w1.x, acc[2]);
                    acc[3] = ffma2(h2, w1.y, acc[3]);
                    acc[4] = ffma2(h2, w2v.x, acc[4]);
                    acc[5] = ffma2(h2, w2v.y, acc[5]);
                }
            }
            if (g < 3) {
#pragma unroll
                for (int i = 0; i < 8; i++) hA[i] = hB[i];
            }
        }

        // reduce across the 4 k-split lanes (lane bits 0,1)
#pragma unroll
        for (int j = 0; j < 6; j++) {
            acc[j] = add2(acc[j], shfl_xor64(acc[j], 1));
            acc[j] = add2(acc[j], shfl_xor64(acc[j], 2));
        }

        if (kg == 0) {
            float gh[12];
#pragma unroll
            for (int j = 0; j < 6; j++) {
                float2 v = unpack2(acc[j]);
                gh[2 * j] = v.x;
                gh[2 * j + 1] = v.y;
            }
            float hp[4] = {hprev0, hprev1, hprev2, hprev3};
            float hnew[4];
#pragma unroll
            for (int u = 0; u < 4; u++) {
                float r = fast_sigmoid(gir[u] + gh[u] + bhh_s[u]);
                float z = fast_sigmoid(giz[u] + gh[4 + u] + bhh_s[4 + u]);
                float n = fast_tanh(gin[u] + r * (gh[8 + u] + bhh_s[8 + u]));
                hnew[u] = (1.0f - z) * n + z * hp[u];
            }
            hprev0 = hnew[0]; hprev1 = hnew[1]; hprev2 = hnew[2]; hprev3 = hnew[3];
            float4 hv4 = make_float4(hnew[0], hnew[1], hnew[2], hnew[3]);
            g_h4[nxt][j0 >> 2][b] = hv4;
            __stcs((float4*)(g_states + ((size_t)s * BB + b) * HH + j0), hv4);
        }

        // grid barrier (monotonic generation counter)
        __threadfence();
        __syncthreads();
        if (tid == 0) {
            unsigned target = (unsigned)NCTA * (unsigned)(s + 1);
            atomicAdd(&g_bar, 1u);
            unsigned v;
            do {
                asm volatile("ld.global.acquire.gpu.u32 %0, [%1];"
                             : "=r"(v) : "l"(&g_bar));
            } while (v < target);
        }
        __syncthreads();
    }
}

// ---------------- Phase 3: tag logits = states @ W_tag^T + b_tag ----------------
__global__ __launch_bounds__(256) void tag_kernel(const float* __restrict__ W_tag,
                                                  const float* __restrict__ b_tag,
                                                  float* __restrict__ out) {
    __shared__ __align__(16) float As[64 * 36];
    __shared__ __align__(16) float Ws[64 * 36];

    const int tid = threadIdx.x;
    const int s = blockIdx.x;
    const int tx = tid & 15, ty = tid >> 4;
    const int b4 = ty * 4, t4 = tx * 4;

    unsigned long long acc[4][4];
#pragma unroll
    for (int i = 0; i < 4; i++)
#pragma unroll
        for (int j = 0; j < 4; j++) acc[i][j] = 0ull;

    for (int k0 = 0; k0 < HH; k0 += 32) {
#pragma unroll
        for (int j = 0; j < 2; j++) {
            int f = tid * 2 + j;
            int r = f >> 3, kq = f & 7;
            float4 v = *(const float4*)(g_states + ((size_t)s * BB + r) * HH + k0 + kq * 4);
            *(float4*)&As[r * 36 + kq * 4] = v;
            float4 w = *(const float4*)(W_tag + (size_t)r * HH + k0 + kq * 4);
            *(float4*)&Ws[r * 36 + kq * 4] = w;
        }
        __syncthreads();
#pragma unroll
        for (int k = 0; k < 32; k += 4) {
            ulonglong2 a2[4];
#pragma unroll
            for (int i = 0; i < 4; i++)
                a2[i] = *(const ulonglong2*)&As[(b4 + i) * 36 + k];
#pragma unroll
            for (int j = 0; j < 4; j++) {
                ulonglong2 w2 = *(const ulonglong2*)&Ws[(t4 + j) * 36 + k];
#pragma unroll
                for (int i = 0; i < 4; i++) {
                    acc[i][j] = ffma2(a2[i].x, w2.x, acc[i][j]);
                    acc[i][j] = ffma2(a2[i].y, w2.y, acc[i][j]);
                }
            }
        }
        __syncthreads();
    }

#pragma unroll
    for (int j = 0; j < 4; j++) {
        int t = t4 + j;
        float bias = b_tag[t];
#pragma unroll
        for (int i = 0; i < 4; i++) {
            int bb = b4 + i;
            float2 v = unpack2(acc[i][j]);
            out[((size_t)bb * SS + s) * TT + t] = v.x + v.y + bias;
        }
    }
}

// ---------------- Phase 4: masked argmax preds ----------------
__global__ void pred_kernel(const void* __restrict__ tokens,
                            float* __restrict__ out, int out_size) {
    const int i = blockIdx.x * blockDim.x + threadIdx.x;  // i = b*512 + s
    if (i >= BB * SS) return;
    const float* lg = out + (size_t)i * TT;
    float best = lg[0];
    int bi = 0;
#pragma unroll 8
    for (int t = 1; t < TT; t++) {
        float v = lg[t];
        if (v > best) { best = v; bi = t; }
    }
    int tk = get_tok(tokens, i);
    long long pred = (tk != 0) ? (long long)bi : 0ll;

    const int NLOGIT = BB * SS * TT;  // 2097152
    int rem = out_size - NLOGIT;
    if (rem >= 2 * BB * SS) {
        long long* po = (long long*)((char*)out + (size_t)NLOGIT * 4);
        po[i] = pred;
    } else if (rem >= BB * SS) {
        out[NLOGIT + i] = (float)pred;
    }
}

// ---------------- launch ----------------
extern "C" void kernel_launch(void* const* d_in, const int* in_sizes, int n_in,
                              void* d_out, int out_size) {
    const void* tokens = d_in[0];
    const float* emb = (const float*)d_in[1];
    const float* W_ih = (const float*)d_in[2];
    const float* W_hh = (const float*)d_in[3];
    const float* b_ih = (const float*)d_in[4];
    const float* b_hh = (const float*)d_in[5];
    const float* W_tag = (const float*)d_in[6];
    const float* b_tag = (const float*)d_in[7];
    float* out = (float*)d_out;

    init_kernel<<<64, 256>>>(tokens);
    gi_kernel<<<dim3(12, 512), 256>>>(tokens, emb, W_ih, b_ih);
    gru_kernel<<<NCTA, 256>>>(W_hh, b_hh);
    tag_kernel<<<SS, 256>>>(W_tag, b_tag, out);
    pred_kernel<<<128, 256>>>(tokens, out, out_size);
}